// round 16
// baseline (speedup 1.0000x reference)
#include <cuda_runtime.h>
#include <cuda_bf16.h>

// IoUMetricLoss: pred_label fp32 [8,19,512,1024], label int32 [8,512,1024]
// out: scalar fp32 = 1 - nanmean(IoU per class), all-NaN -> 0.5
//
// R16: 3 graph-ordered kernels. A: streaming argmax (R15: 6.73 TB/s,
// DRAM 85%, occ 67% @ regs=37/6 CTA/SM) now reg-capped to 32 via
// __launch_bounds__(256,8) -> 8 CTA/SM, targeting ~90% DRAM. B: histogram
// with 4 independent group-loads per thread (3 unconditional + 1
// predicated) instead of a dependent grid-stride chain. C: finalize +
// state reset. No done-counters anywhere (R15 lesson: a single
// atomic-with-return address serializes at ~32cyc/op).

#define NUM_CLASSES 19
#define CM_BINS (NUM_CLASSES * NUM_CLASSES)   // 361
#define HW_SHIFT 19                  // 512*1024 = 2^19
#define HW (1 << HW_SHIFT)
#define TOTAL_PIX (8 * HW)           // 4194304
#define VEC_GROUPS (TOTAL_PIX / 4)   // 1048576
#define A_BLOCK 256
#define A_GRID (VEC_GROUPS / A_BLOCK)          // 4096
#define B_BLOCK 1024
#define B_GRID 296                   // 2 CTA/SM, perfectly balanced
#define B_STRIDE (B_GRID * B_BLOCK)  // 303104
#define B_HISTS 8                    // 4 warps share one smem hist

// Scratch + accumulators (no cudaMalloc allowed). g_idx: 4 packed uint8
// argmax indices per vec-group. g_cm statically zero; C re-zeros it after
// reading so every graph replay sees clean state.
__device__ unsigned int g_idx[VEC_GROUPS];     // 4 MB scratch
__device__ unsigned int g_cm[CM_BINS];

__device__ __forceinline__ void amax_step(float v, float& bv, int& bi, int c) {
    float m = fmaxf(bv, v);
    bi = (v > bv) ? c : bi;
    bv = m;
}

// ---------- Kernel A: pure streaming argmax, reg-capped for 8 CTA/SM ----------
__global__ void __launch_bounds__(A_BLOCK, 8)
iou_argmax_kernel(const float* __restrict__ pred) {
    const unsigned t  = blockIdx.x * A_BLOCK + threadIdx.x;  // vec-group id
    const unsigned P  = t << 2;
    const unsigned b  = P >> HW_SHIFT;
    const unsigned hw = P & (HW - 1);

    const float* base = pred + ((size_t)b * NUM_CLASSES << HW_SHIFT) + hw;

    float4 bv = __ldcs((const float4*)base);
    int i0 = 0, i1 = 0, i2 = 0, i3 = 0;
    #pragma unroll
    for (int c = 1; c < NUM_CLASSES; c++) {
        float4 v = __ldcs((const float4*)(base + ((size_t)c << HW_SHIFT)));
        amax_step(v.x, bv.x, i0, c);
        amax_step(v.y, bv.y, i1, c);
        amax_step(v.z, bv.z, i2, c);
        amax_step(v.w, bv.w, i3, c);
    }
    // default-cached store: B reads this right after -> mostly L2-hot
    g_idx[t] = (unsigned)i0 | ((unsigned)i1 << 8) |
               ((unsigned)i2 << 16) | ((unsigned)i3 << 24);
}

// ---------- Kernel B: histogram, 4 independent groups/thread ----------
__global__ void __launch_bounds__(B_BLOCK)
iou_hist_kernel(const int* __restrict__ label) {
    __shared__ unsigned int s_cm[B_HISTS][CM_BINS];   // 11.5 KB

    const int tid  = threadIdx.x;
    const int hist = tid >> 7;            // 4 warps (128 threads) per hist

    for (int i = tid; i < B_HISTS * CM_BINS; i += B_BLOCK)
        ((unsigned int*)s_cm)[i] = 0u;
    __syncthreads();

    // 4 fixed-stride group slots per thread; slots 0-2 always valid
    // (3*B_STRIDE = 909312 < VEC_GROUPS), slot 3 predicated.
    const unsigned t0 = blockIdx.x * B_BLOCK + tid;
    const bool has3 = (t0 + 3u * B_STRIDE) < VEC_GROUPS;

    // all independent, issued back-to-back (coalesced per iteration)
    unsigned pk0 = g_idx[t0];
    unsigned pk1 = g_idx[t0 + B_STRIDE];
    unsigned pk2 = g_idx[t0 + 2u * B_STRIDE];
    unsigned pk3 = has3 ? g_idx[t0 + 3u * B_STRIDE] : 0u;
    int4 l0 = __ldcs((const int4*)(label + ((size_t)t0 << 2)));
    int4 l1 = __ldcs((const int4*)(label + ((size_t)(t0 + B_STRIDE) << 2)));
    int4 l2 = __ldcs((const int4*)(label + ((size_t)(t0 + 2u * B_STRIDE) << 2)));
    int4 l3 = has3 ? __ldcs((const int4*)(label + ((size_t)(t0 + 3u * B_STRIDE) << 2)))
                   : make_int4(-1, -1, -1, -1);

    #define ACC4(lv, pk)                                                       \
        {                                                                      \
            int p0 = (pk) & 0xFF, p1 = ((pk) >> 8) & 0xFF;                     \
            int p2 = ((pk) >> 16) & 0xFF, p3 = ((pk) >> 24) & 0xFF;            \
            if ((lv).x >= 0) atomicAdd(&s_cm[hist][(lv).x * NUM_CLASSES + p0], 1u); \
            if ((lv).y >= 0) atomicAdd(&s_cm[hist][(lv).y * NUM_CLASSES + p1], 1u); \
            if ((lv).z >= 0) atomicAdd(&s_cm[hist][(lv).z * NUM_CLASSES + p2], 1u); \
            if ((lv).w >= 0) atomicAdd(&s_cm[hist][(lv).w * NUM_CLASSES + p3], 1u); \
        }
    ACC4(l0, pk0); ACC4(l1, pk1); ACC4(l2, pk2); ACC4(l3, pk3);
    #undef ACC4

    __syncthreads();

    // block reduce -> global CM via RED (result unused -> fast path)
    for (int bin = tid; bin < CM_BINS; bin += B_BLOCK) {
        unsigned s = 0u;
        #pragma unroll
        for (int h = 0; h < B_HISTS; h++) s += s_cm[h][bin];
        if (s) atomicAdd(&g_cm[bin], s);
    }
    // no done-counter, no fence: kernel boundary orders B before C
}

// ---------- Kernel C: finalize + state reset ----------
__global__ void iou_finalize_kernel(float* __restrict__ out) {
    const int tid = threadIdx.x;     // 64 threads
    __shared__ float s_loss;

    if (tid < 32) {
        const int c = tid;
        float iou_sum = 0.0f;
        int   valid   = 0;
        if (c < NUM_CLASSES) {
            unsigned long long lab = 0, pr = 0;
            #pragma unroll
            for (int k = 0; k < NUM_CLASSES; k++) {
                lab += g_cm[c * NUM_CLASSES + k];   // row sum: area_label
                pr  += g_cm[k * NUM_CLASSES + c];   // col sum: area_pred
            }
            unsigned long long inter = g_cm[c * NUM_CLASSES + c];
            unsigned long long uni   = lab + pr - inter;
            if (uni > 0ULL) {
                iou_sum = (float)inter / (float)uni;
                valid   = 1;
            }
            // uni == 0 -> 0/0 = NaN in reference, excluded by nanmean
        }
        #pragma unroll
        for (int o = 16; o > 0; o >>= 1) {
            iou_sum += __shfl_down_sync(0xFFFFFFFFu, iou_sum, o);
            valid   += __shfl_down_sync(0xFFFFFFFFu, valid, o);
        }
        if (c == 0)
            s_loss = (valid > 0) ? (1.0f - iou_sum / (float)valid) : 0.5f;
    }
    __syncthreads();
    // reset global CM for the next graph replay, then emit
    for (int i = tid; i < CM_BINS; i += blockDim.x)
        g_cm[i] = 0u;
    if (tid == 0)
        *out = s_loss;
}

extern "C" void kernel_launch(void* const* d_in, const int* in_sizes, int n_in,
                              void* d_out, int out_size) {
    // pred = 79,691,776 elems; label = 4,194,304 (resolve by size).
    const float* pred;
    const int*   label;
    if (in_sizes[0] >= in_sizes[1]) {
        pred  = (const float*)d_in[0];
        label = (const int*)d_in[1];
    } else {
        pred  = (const float*)d_in[1];
        label = (const int*)d_in[0];
    }
    float* out = (float*)d_out;

    iou_argmax_kernel<<<A_GRID, A_BLOCK>>>(pred);
    iou_hist_kernel<<<B_GRID, B_BLOCK>>>(label);
    iou_finalize_kernel<<<1, 64>>>(out);
}

// round 17
// speedup vs baseline: 1.0371x; 1.0371x over previous
#include <cuda_runtime.h>
#include <cuda_bf16.h>

// IoUMetricLoss: pred_label fp32 [8,19,512,1024], label int32 [8,512,1024]
// out: scalar fp32 = 1 - nanmean(IoU per class), all-NaN -> 0.5
//
// R17: exact R15 bodies (best: 55.8us; A=6.73 TB/s, R16's occ/reg
// experiments regressed and are reverted) + programmatic dependent launch:
// B and C carry programmaticStreamSerializationAllowed, A/B call
// cudaTriggerProgrammaticLaunchCompletion(), and B front-loads its smem
// zeroing + all label loads BEFORE cudaGridDependencySynchronize() so
// they overlap A's drain wave. Worst case degenerates to R15 serial.

#define NUM_CLASSES 19
#define CM_BINS (NUM_CLASSES * NUM_CLASSES)   // 361
#define HW_SHIFT 19                  // 512*1024 = 2^19
#define HW (1 << HW_SHIFT)
#define TOTAL_PIX (8 * HW)           // 4194304
#define VEC_GROUPS (TOTAL_PIX / 4)   // 1048576
#define A_BLOCK 256
#define A_GRID (VEC_GROUPS / A_BLOCK)          // 4096
#define B_BLOCK 1024
#define B_GRID 296                   // 2 CTA/SM
#define B_STRIDE (B_GRID * B_BLOCK)  // 303104
#define B_HISTS 8                    // 4 warps share one smem hist

// Scratch + accumulators (no cudaMalloc allowed). g_idx: 4 packed uint8
// argmax indices per vec-group. g_cm statically zero; C re-zeros it after
// reading so every graph replay sees clean state.
__device__ unsigned int g_idx[VEC_GROUPS];     // 4 MB scratch
__device__ unsigned int g_cm[CM_BINS];

__device__ __forceinline__ void amax_step(float v, float& bv, int& bi, int c) {
    float m = fmaxf(bv, v);
    bi = (v > bv) ? c : bi;
    bv = m;
}

// ---------- Kernel A: pure streaming argmax (R15-proven, 6.73 TB/s) ----------
__global__ void __launch_bounds__(A_BLOCK)
iou_argmax_kernel(const float* __restrict__ pred) {
    // allow the dependent hist kernel to start launching on draining SMs
    cudaTriggerProgrammaticLaunchCompletion();

    const unsigned t  = blockIdx.x * A_BLOCK + threadIdx.x;  // vec-group id
    const unsigned P  = t << 2;
    const unsigned b  = P >> HW_SHIFT;
    const unsigned hw = P & (HW - 1);

    const float* base = pred + ((size_t)b * NUM_CLASSES << HW_SHIFT) + hw;

    float4 bv = __ldcs((const float4*)base);
    int i0 = 0, i1 = 0, i2 = 0, i3 = 0;
    #pragma unroll
    for (int c = 1; c < NUM_CLASSES; c++) {
        float4 v = __ldcs((const float4*)(base + ((size_t)c << HW_SHIFT)));
        amax_step(v.x, bv.x, i0, c);
        amax_step(v.y, bv.y, i1, c);
        amax_step(v.z, bv.z, i2, c);
        amax_step(v.w, bv.w, i3, c);
    }
    // default-cached store: B reads this right after -> mostly L2-hot
    g_idx[t] = (unsigned)i0 | ((unsigned)i1 << 8) |
               ((unsigned)i2 << 16) | ((unsigned)i3 << 24);
}

// ---------- Kernel B: histogram; labels + zeroing overlap A via PDL ----------
__global__ void __launch_bounds__(B_BLOCK)
iou_hist_kernel(const int* __restrict__ label) {
    __shared__ unsigned int s_cm[B_HISTS][CM_BINS];   // 11.5 KB

    const int tid  = threadIdx.x;
    const int hist = tid >> 7;            // 4 warps (128 threads) per hist

    // ---- pre-sync phase: independent of A ----
    for (int i = tid; i < B_HISTS * CM_BINS; i += B_BLOCK)
        ((unsigned int*)s_cm)[i] = 0u;

    // 4 fixed-stride group slots; slots 0-2 always valid
    // (3*B_STRIDE = 909312 < VEC_GROUPS), slot 3 predicated.
    const unsigned t0 = blockIdx.x * B_BLOCK + tid;
    const bool has3 = (t0 + 3u * B_STRIDE) < VEC_GROUPS;

    int4 l0 = __ldcs((const int4*)(label + ((size_t)t0 << 2)));
    int4 l1 = __ldcs((const int4*)(label + ((size_t)(t0 + B_STRIDE) << 2)));
    int4 l2 = __ldcs((const int4*)(label + ((size_t)(t0 + 2u * B_STRIDE) << 2)));
    int4 l3 = has3 ? __ldcs((const int4*)(label + ((size_t)(t0 + 3u * B_STRIDE) << 2)))
                   : make_int4(-1, -1, -1, -1);

    cudaTriggerProgrammaticLaunchCompletion();   // let C launch early too
    cudaGridDependencySynchronize();             // wait for A's g_idx
    __syncthreads();                             // smem zero visible

    // ---- post-sync phase: consume g_idx (L2-hot) ----
    unsigned pk0 = g_idx[t0];
    unsigned pk1 = g_idx[t0 + B_STRIDE];
    unsigned pk2 = g_idx[t0 + 2u * B_STRIDE];
    unsigned pk3 = has3 ? g_idx[t0 + 3u * B_STRIDE] : 0u;

    #define ACC4(lv, pk)                                                       \
        {                                                                      \
            int p0 = (pk) & 0xFF, p1 = ((pk) >> 8) & 0xFF;                     \
            int p2 = ((pk) >> 16) & 0xFF, p3 = ((pk) >> 24) & 0xFF;            \
            if ((lv).x >= 0) atomicAdd(&s_cm[hist][(lv).x * NUM_CLASSES + p0], 1u); \
            if ((lv).y >= 0) atomicAdd(&s_cm[hist][(lv).y * NUM_CLASSES + p1], 1u); \
            if ((lv).z >= 0) atomicAdd(&s_cm[hist][(lv).z * NUM_CLASSES + p2], 1u); \
            if ((lv).w >= 0) atomicAdd(&s_cm[hist][(lv).w * NUM_CLASSES + p3], 1u); \
        }
    ACC4(l0, pk0); ACC4(l1, pk1); ACC4(l2, pk2); ACC4(l3, pk3);
    #undef ACC4

    __syncthreads();

    // block reduce -> global CM via RED (result unused -> fast path)
    for (int bin = tid; bin < CM_BINS; bin += B_BLOCK) {
        unsigned s = 0u;
        #pragma unroll
        for (int h = 0; h < B_HISTS; h++) s += s_cm[h][bin];
        if (s) atomicAdd(&g_cm[bin], s);
    }
    // no done-counter, no fence: kernel boundary orders B before C
}

// ---------- Kernel C: finalize + state reset ----------
__global__ void iou_finalize_kernel(float* __restrict__ out) {
    cudaGridDependencySynchronize();             // wait for B's g_cm
    const int tid = threadIdx.x;     // 64 threads
    __shared__ float s_loss;

    if (tid < 32) {
        const int c = tid;
        float iou_sum = 0.0f;
        int   valid   = 0;
        if (c < NUM_CLASSES) {
            unsigned long long lab = 0, pr = 0;
            #pragma unroll
            for (int k = 0; k < NUM_CLASSES; k++) {
                lab += g_cm[c * NUM_CLASSES + k];   // row sum: area_label
                pr  += g_cm[k * NUM_CLASSES + c];   // col sum: area_pred
            }
            unsigned long long inter = g_cm[c * NUM_CLASSES + c];
            unsigned long long uni   = lab + pr - inter;
            if (uni > 0ULL) {
                iou_sum = (float)inter / (float)uni;
                valid   = 1;
            }
            // uni == 0 -> 0/0 = NaN in reference, excluded by nanmean
        }
        #pragma unroll
        for (int o = 16; o > 0; o >>= 1) {
            iou_sum += __shfl_down_sync(0xFFFFFFFFu, iou_sum, o);
            valid   += __shfl_down_sync(0xFFFFFFFFu, valid, o);
        }
        if (c == 0)
            s_loss = (valid > 0) ? (1.0f - iou_sum / (float)valid) : 0.5f;
    }
    __syncthreads();
    // reset global CM for the next graph replay, then emit
    for (int i = tid; i < CM_BINS; i += blockDim.x)
        g_cm[i] = 0u;
    if (tid == 0)
        *out = s_loss;
}

extern "C" void kernel_launch(void* const* d_in, const int* in_sizes, int n_in,
                              void* d_out, int out_size) {
    // pred = 79,691,776 elems; label = 4,194,304 (resolve by size).
    const float* pred;
    const int*   label;
    if (in_sizes[0] >= in_sizes[1]) {
        pred  = (const float*)d_in[0];
        label = (const int*)d_in[1];
    } else {
        pred  = (const float*)d_in[1];
        label = (const int*)d_in[0];
    }
    float* out = (float*)d_out;

    // A: normal launch
    iou_argmax_kernel<<<A_GRID, A_BLOCK>>>(pred);

    // B, C: programmatic dependent launches (overlap with predecessor tail)
    cudaLaunchAttribute pdl[1];
    pdl[0].id = cudaLaunchAttributeProgrammaticStreamSerialization;
    pdl[0].val.programmaticStreamSerializationAllowed = 1;

    cudaLaunchConfig_t cfgB = {};
    cfgB.gridDim  = dim3(B_GRID);
    cfgB.blockDim = dim3(B_BLOCK);
    cfgB.stream   = 0;
    cfgB.attrs    = pdl;
    cfgB.numAttrs = 1;
    cudaLaunchKernelEx(&cfgB, iou_hist_kernel, label);

    cudaLaunchConfig_t cfgC = {};
    cfgC.gridDim  = dim3(1);
    cfgC.blockDim = dim3(64);
    cfgC.stream   = 0;
    cfgC.attrs    = pdl;
    cfgC.numAttrs = 1;
    cudaLaunchKernelEx(&cfgC, iou_finalize_kernel, out);
}